// round 12
// baseline (speedup 1.0000x reference)
#include <cuda_runtime.h>

// SpatialDeformer3D via SMEM-tiled trilinear gather, v9:
//  - v7 core (best proven: 78.6us) with 1024-thread CTAs and 16x16x32 tile:
//    2 CTAs/SM x 1024 thr = 100% theoretical occupancy, and the h-halo is
//    amortized over 16 output planes (fill cost per voxel -19%)
//  - +/-2 halo, depth-2 def pipeline, __ldcs def stream, __stcs output,
//    fast path = base + 8 immediate-offset LDS, rare fallback = exact
//    reference math with clamps + global gathers
//
//   X:           (2, 160, 192, 160, 2)  float32
//   deformation: (2, 160, 192, 160, 3)  float32
//   out:         (2, 160, 192, 160, 1)  float32

#define BB 2
#define HH 160
#define WW 192
#define DD 160
#define WD (WW * DD)

#define TH 16
#define TW 16
#define TD 32
#define RLO 2              // halo below; +3 above (x1=x0+1) => extent T+5
#define HS (TH + 5)        // 21
#define WS (TW + 5)        // 21
#define DS (TD + 5)        // 37
#define NROWS (HS * WS)    // 441
#define SVOL (NROWS * DS)  // 16317 floats = 65268 B

#define NTHR 1024
#define NWARP (NTHR / 32)  // 32

__global__ __launch_bounds__(NTHR, 2) void deform3d_tile9_kernel(
    const float* __restrict__ X,
    const float* __restrict__ def,
    float* __restrict__ out)
{
    extern __shared__ float s[];

    const int b  = blockIdx.z / (HH / TH);
    const int hz = blockIdx.z % (HH / TH);
    const int h0 = hz * TH;
    const int w0 = blockIdx.y * TW;
    const int d0 = blockIdx.x * TD;

    const int lane = threadIdx.x;          // 0..31 -> d
    const int ty   = threadIdx.y;          // 0..31
    const int wy   = ty & 15;              // -> w
    const int hg   = ty >> 4;              // 0/1 -> h half (8 planes each)
    const int warpId = ty;                 // 32 warps

    const float* Xb = X + (size_t)b * (HH * WW * DD * 2);

    const int yb = h0 - RLO;
    const int xb = w0 - RLO;
    const int zb = d0 - RLO;

    const int d = d0 + lane;
    const int w = w0 + wy;
    const int hbase = h0 + hg * (TH / 2);

    const int vox0 = ((b * HH + hbase) * WW + w) * DD + d;

    // ---- Pipeline prologue: def loads for iterations 0, 1 issued before
    //      the SMEM fill so the fill hides their DRAM latency. ----
    float bx0, by0, bz0, bx1, by1, bz1;
    {
        const float* dp0 = def + (size_t)vox0 * 3;
        const float* dp1 = dp0 + (size_t)WD * 3;
        bx0 = __ldcs(dp0 + 0); by0 = __ldcs(dp0 + 1); bz0 = __ldcs(dp0 + 2);
        bx1 = __ldcs(dp1 + 0); by1 = __ldcs(dp1 + 1); bz1 = __ldcs(dp1 + 2);
    }

    // ---- SMEM fill: one warp per (hy,wx) row, div-free decomposition ----
    {
        const int ezA = min(max(zb + lane, 0), DD - 1) * 2;
        const int ezB = min(max(zb + lane + 32, 0), DD - 1) * 2;

        int hy = warpId / WS;              // one-time division (warpId < 64)
        int wx = warpId - hy * WS;
        for (int row = warpId; row < NROWS; row += NWARP) {
            int gy = min(max(yb + hy, 0), HH - 1);
            int gx = min(max(xb + wx, 0), WW - 1);
            const float* src = Xb + (size_t)(gy * WW + gx) * (DD * 2);
            float* dst = s + row * DS;
            dst[lane] = __ldg(src + ezA);
            if (lane < DS - 32)
                dst[lane + 32] = __ldg(src + ezB);
            wx += NWARP;
            while (wx >= WS) { wx -= WS; hy++; }   // NWARP(32) < 2*WS(42)
        }
    }
    __syncthreads();

    // Fast-path bounds: corner index c0 must satisfy clip-identity AND
    // in-tile:  c0 in [max(0, base), min(base + S - 2, LIM - 2)].
    const int loY = max(0, yb), rngY = min(yb + HS - 2, HH - 2) - loY;
    const int loX = max(0, xb), rngX = min(xb + WS - 2, WW - 2) - loX;
    const int loZ = max(0, zb), rngZ = min(zb + DS - 2, DD - 2) - loZ;

    const float wf = (float)w;
    const float df = (float)d;
    float hf = (float)hbase;

    int vox = vox0;
    const float* dpn = def + ((size_t)vox0 + (size_t)2 * WD) * 3; // it+2 loads

    #pragma unroll
    for (int hh = 0; hh < TH / 2; hh++, vox += WD, hf += 1.0f) {
        // Consume the stage loaded 2 iterations ago.
        float dx, dy, dzv;
        if ((hh & 1) == 0) { dx = bx0; dy = by0; dzv = bz0; }
        else               { dx = bx1; dy = by1; dzv = bz1; }

        // Refill this stage with iteration hh+2.
        if (hh < TH / 2 - 2) {
            float nx = __ldcs(dpn + 0);
            float ny = __ldcs(dpn + 1);
            float nz = __ldcs(dpn + 2);
            if ((hh & 1) == 0) { bx0 = nx; by0 = ny; bz0 = nz; }
            else               { bx1 = nx; by1 = ny; bz1 = nz; }
            dpn += (size_t)WD * 3;
        }

        float x = wf + dx;          // def[...,0] -> W axis
        float y = hf + dy;          // def[...,1] -> H axis
        float z = df + dzv;         // def[...,2] -> D axis

        int x0 = __float2int_rd(x);
        int y0 = __float2int_rd(y);
        int z0 = __float2int_rd(z);

        bool fast = ((unsigned)(y0 - loY) <= (unsigned)rngY) &
                    ((unsigned)(x0 - loX) <= (unsigned)rngX) &
                    ((unsigned)(z0 - loZ) <= (unsigned)rngZ);

        float res;
        if (fast) {
            // clip == identity here: x1 = x0+1 etc., all taps in SMEM tile.
            float x0f = (float)x0, y0f = (float)y0, z0f = (float)z0;
            float wx1 = x - x0f, wx0 = (x0f + 1.0f) - x;
            float wy1 = y - y0f, wy0 = (y0f + 1.0f) - y;
            float wz1 = z - z0f, wz0 = (z0f + 1.0f) - z;

            int base = ((y0 - yb) * WS + (x0 - xb)) * DS + (z0 - zb);

            float p000 = s[base];
            float p001 = s[base + 1];
            float p010 = s[base + DS];
            float p011 = s[base + DS + 1];
            float p100 = s[base + WS * DS];
            float p101 = s[base + WS * DS + 1];
            float p110 = s[base + WS * DS + DS];
            float p111 = s[base + WS * DS + DS + 1];

            res = wy0 * (wx0 * (wz0 * p000 + wz1 * p001) +
                         wx1 * (wz0 * p010 + wz1 * p011)) +
                  wy1 * (wx0 * (wz0 * p100 + wz1 * p101) +
                         wx1 * (wz0 * p110 + wz1 * p111));
        } else {
            // Exact reference path: clip each corner independently; weights
            // from CLIPPED coords so out-of-range dims cancel to zero.
            int x1 = x0 + 1, y1 = y0 + 1, z1 = z0 + 1;
            x0 = min(max(x0, 0), WW - 1);  x1 = min(max(x1, 0), WW - 1);
            y0 = min(max(y0, 0), HH - 1);  y1 = min(max(y1, 0), HH - 1);
            z0 = min(max(z0, 0), DD - 1);  z1 = min(max(z1, 0), DD - 1);

            float wx0 = (float)x1 - x, wx1 = x - (float)x0;
            float wy0 = (float)y1 - y, wy1 = y - (float)y0;
            float wz0 = (float)z1 - z, wz1 = z - (float)z0;

            int i00 = (y0 * WW + x0) * (DD * 2);
            int i01 = (y0 * WW + x1) * (DD * 2);
            int i10 = (y1 * WW + x0) * (DD * 2);
            int i11 = (y1 * WW + x1) * (DD * 2);
            int z0e = z0 * 2, z1e = z1 * 2;
            float p000 = __ldg(Xb + i00 + z0e), p001 = __ldg(Xb + i00 + z1e);
            float p010 = __ldg(Xb + i01 + z0e), p011 = __ldg(Xb + i01 + z1e);
            float p100 = __ldg(Xb + i10 + z0e), p101 = __ldg(Xb + i10 + z1e);
            float p110 = __ldg(Xb + i11 + z0e), p111 = __ldg(Xb + i11 + z1e);

            res = wy0 * (wx0 * (wz0 * p000 + wz1 * p001) +
                         wx1 * (wz0 * p010 + wz1 * p011)) +
                  wy1 * (wx0 * (wz0 * p100 + wz1 * p101) +
                         wx1 * (wz0 * p110 + wz1 * p111));
        }

        __stcs(out + vox, res);   // streaming store: keep L2 for X reuse
    }
}

extern "C" void kernel_launch(void* const* d_in, const int* in_sizes, int n_in,
                              void* d_out, int out_size)
{
    const float* X   = (const float*)d_in[0];
    const float* def = (const float*)d_in[1];
    float* out = (float*)d_out;

    cudaFuncSetAttribute(deform3d_tile9_kernel,
                         cudaFuncAttributeMaxDynamicSharedMemorySize,
                         SVOL * (int)sizeof(float));

    dim3 grid(DD / TD, WW / TW, BB * (HH / TH));   // (5, 12, 20) = 1200 CTAs
    dim3 block(32, 32, 1);                          // 1024 threads
    deform3d_tile9_kernel<<<grid, block, SVOL * sizeof(float)>>>(X, def, out);
}

// round 14
// speedup vs baseline: 1.0325x; 1.0325x over previous
#include <cuda_runtime.h>

// SpatialDeformer3D via SMEM-tiled trilinear gather, v10:
//  - v9 core (16x16x32 tile, 1024 thr, 2 CTAs/SM, <=32 regs)
//  - BATCHED fill: each warp's rows processed in 2 groups of 7; all 14 LDGs
//    of a group issued back-to-back before any STS -> DRAM latency exposed
//    ~2x600cy per warp instead of ~serial per row
//  - +/-2 halo, depth-2 def register pipeline, __ldcs def, __stcs out,
//    fast path = base + 8 immediate-offset LDS, rare fallback = exact
//    reference math with clamps + global gathers
//
//   X:           (2, 160, 192, 160, 2)  float32
//   deformation: (2, 160, 192, 160, 3)  float32
//   out:         (2, 160, 192, 160, 1)  float32

#define BB 2
#define HH 160
#define WW 192
#define DD 160
#define WD (WW * DD)

#define TH 16
#define TW 16
#define TD 32
#define RLO 2              // halo below; +3 above (x1=x0+1) => extent T+5
#define HS (TH + 5)        // 21
#define WS (TW + 5)        // 21
#define DS (TD + 5)        // 37
#define NROWS (HS * WS)    // 441
#define SVOL (NROWS * DS)  // 16317 floats = 65268 B

#define NTHR 1024
#define NWARP (NTHR / 32)  // 32
#define FG 7               // fill group size (rows per warp per batch)

__global__ __launch_bounds__(NTHR, 2) void deform3d_tile10_kernel(
    const float* __restrict__ X,
    const float* __restrict__ def,
    float* __restrict__ out)
{
    extern __shared__ float s[];

    const int b  = blockIdx.z / (HH / TH);
    const int hz = blockIdx.z % (HH / TH);
    const int h0 = hz * TH;
    const int w0 = blockIdx.y * TW;
    const int d0 = blockIdx.x * TD;

    const int lane = threadIdx.x;          // 0..31 -> d
    const int ty   = threadIdx.y;          // 0..31
    const int wy   = ty & 15;              // -> w
    const int hg   = ty >> 4;              // 0/1 -> h half (8 planes each)
    const int warpId = ty;                 // 32 warps

    const float* Xb = X + (size_t)b * (HH * WW * DD * 2);

    const int yb = h0 - RLO;
    const int xb = w0 - RLO;
    const int zb = d0 - RLO;

    const int d = d0 + lane;
    const int w = w0 + wy;
    const int hbase = h0 + hg * (TH / 2);

    const int vox0 = ((b * HH + hbase) * WW + w) * DD + d;

    // ---- Pipeline prologue: def loads for iterations 0, 1 issued first so
    //      the fill hides their DRAM latency. ----
    float bx0, by0, bz0, bx1, by1, bz1;
    {
        const float* dp0 = def + (size_t)vox0 * 3;
        const float* dp1 = dp0 + (size_t)WD * 3;
        bx0 = __ldcs(dp0 + 0); by0 = __ldcs(dp0 + 1); bz0 = __ldcs(dp0 + 2);
        bx1 = __ldcs(dp1 + 0); by1 = __ldcs(dp1 + 1); bz1 = __ldcs(dp1 + 2);
    }

    // ---- SMEM fill: one warp per (hy,wx) row; rows batched in groups of 7
    //      so all group LDGs are outstanding before the first STS. ----
    {
        const int ezA = min(max(zb + lane, 0), DD - 1) * 2;
        const int ezB = min(max(zb + lane + 32, 0), DD - 1) * 2;

        int hy = warpId / WS;
        int wx = warpId - hy * WS;

        #pragma unroll
        for (int g = 0; g < 2; g++) {
            const int rbase = warpId + g * (NWARP * FG);
            float vA[FG], vB[FG];

            // Load phase: issue all LDGs of the group back-to-back.
            #pragma unroll
            for (int j = 0; j < FG; j++) {
                int row = rbase + j * NWARP;
                if (row < NROWS) {
                    int gy = min(max(yb + hy, 0), HH - 1);
                    int gx = min(max(xb + wx, 0), WW - 1);
                    const float* src = Xb + (size_t)(gy * WW + gx) * (DD * 2);
                    vA[j] = __ldg(src + ezA);
                    vB[j] = (lane < DS - 32) ? __ldg(src + ezB) : 0.0f;
                    wx += NWARP;
                    while (wx >= WS) { wx -= WS; hy++; }
                }
            }

            // Store phase.
            #pragma unroll
            for (int j = 0; j < FG; j++) {
                int row = rbase + j * NWARP;
                if (row < NROWS) {
                    float* dst = s + row * DS;
                    dst[lane] = vA[j];
                    if (lane < DS - 32)
                        dst[lane + 32] = vB[j];
                }
            }
        }
    }
    __syncthreads();

    // Fast-path bounds: corner index c0 must satisfy clip-identity AND
    // in-tile:  c0 in [max(0, base), min(base + S - 2, LIM - 2)].
    const int loY = max(0, yb), rngY = min(yb + HS - 2, HH - 2) - loY;
    const int loX = max(0, xb), rngX = min(xb + WS - 2, WW - 2) - loX;
    const int loZ = max(0, zb), rngZ = min(zb + DS - 2, DD - 2) - loZ;

    const float wf = (float)w;
    const float df = (float)d;
    float hf = (float)hbase;

    int vox = vox0;
    const float* dpn = def + ((size_t)vox0 + (size_t)2 * WD) * 3; // it+2 loads

    #pragma unroll
    for (int hh = 0; hh < TH / 2; hh++, vox += WD, hf += 1.0f) {
        // Consume the stage loaded 2 iterations ago.
        float dx, dy, dzv;
        if ((hh & 1) == 0) { dx = bx0; dy = by0; dzv = bz0; }
        else               { dx = bx1; dy = by1; dzv = bz1; }

        // Refill this stage with iteration hh+2.
        if (hh < TH / 2 - 2) {
            float nx = __ldcs(dpn + 0);
            float ny = __ldcs(dpn + 1);
            float nz = __ldcs(dpn + 2);
            if ((hh & 1) == 0) { bx0 = nx; by0 = ny; bz0 = nz; }
            else               { bx1 = nx; by1 = ny; bz1 = nz; }
            dpn += (size_t)WD * 3;
        }

        float x = wf + dx;          // def[...,0] -> W axis
        float y = hf + dy;          // def[...,1] -> H axis
        float z = df + dzv;         // def[...,2] -> D axis

        int x0 = __float2int_rd(x);
        int y0 = __float2int_rd(y);
        int z0 = __float2int_rd(z);

        bool fast = ((unsigned)(y0 - loY) <= (unsigned)rngY) &
                    ((unsigned)(x0 - loX) <= (unsigned)rngX) &
                    ((unsigned)(z0 - loZ) <= (unsigned)rngZ);

        float res;
        if (fast) {
            // clip == identity here: x1 = x0+1 etc., all taps in SMEM tile.
            float x0f = (float)x0, y0f = (float)y0, z0f = (float)z0;
            float wx1 = x - x0f, wx0 = (x0f + 1.0f) - x;
            float wy1 = y - y0f, wy0 = (y0f + 1.0f) - y;
            float wz1 = z - z0f, wz0 = (z0f + 1.0f) - z;

            int base = ((y0 - yb) * WS + (x0 - xb)) * DS + (z0 - zb);

            float p000 = s[base];
            float p001 = s[base + 1];
            float p010 = s[base + DS];
            float p011 = s[base + DS + 1];
            float p100 = s[base + WS * DS];
            float p101 = s[base + WS * DS + 1];
            float p110 = s[base + WS * DS + DS];
            float p111 = s[base + WS * DS + DS + 1];

            res = wy0 * (wx0 * (wz0 * p000 + wz1 * p001) +
                         wx1 * (wz0 * p010 + wz1 * p011)) +
                  wy1 * (wx0 * (wz0 * p100 + wz1 * p101) +
                         wx1 * (wz0 * p110 + wz1 * p111));
        } else {
            // Exact reference path: clip each corner independently; weights
            // from CLIPPED coords so out-of-range dims cancel to zero.
            int x1 = x0 + 1, y1 = y0 + 1, z1 = z0 + 1;
            x0 = min(max(x0, 0), WW - 1);  x1 = min(max(x1, 0), WW - 1);
            y0 = min(max(y0, 0), HH - 1);  y1 = min(max(y1, 0), HH - 1);
            z0 = min(max(z0, 0), DD - 1);  z1 = min(max(z1, 0), DD - 1);

            float wx0 = (float)x1 - x, wx1 = x - (float)x0;
            float wy0 = (float)y1 - y, wy1 = y - (float)y0;
            float wz0 = (float)z1 - z, wz1 = z - (float)z0;

            int i00 = (y0 * WW + x0) * (DD * 2);
            int i01 = (y0 * WW + x1) * (DD * 2);
            int i10 = (y1 * WW + x0) * (DD * 2);
            int i11 = (y1 * WW + x1) * (DD * 2);
            int z0e = z0 * 2, z1e = z1 * 2;
            float p000 = __ldg(Xb + i00 + z0e), p001 = __ldg(Xb + i00 + z1e);
            float p010 = __ldg(Xb + i01 + z0e), p011 = __ldg(Xb + i01 + z1e);
            float p100 = __ldg(Xb + i10 + z0e), p101 = __ldg(Xb + i10 + z1e);
            float p110 = __ldg(Xb + i11 + z0e), p111 = __ldg(Xb + i11 + z1e);

            res = wy0 * (wx0 * (wz0 * p000 + wz1 * p001) +
                         wx1 * (wz0 * p010 + wz1 * p011)) +
                  wy1 * (wx0 * (wz0 * p100 + wz1 * p101) +
                         wx1 * (wz0 * p110 + wz1 * p111));
        }

        __stcs(out + vox, res);   // streaming store: keep L2 for X reuse
    }
}

extern "C" void kernel_launch(void* const* d_in, const int* in_sizes, int n_in,
                              void* d_out, int out_size)
{
    const float* X   = (const float*)d_in[0];
    const float* def = (const float*)d_in[1];
    float* out = (float*)d_out;

    cudaFuncSetAttribute(deform3d_tile10_kernel,
                         cudaFuncAttributeMaxDynamicSharedMemorySize,
                         SVOL * (int)sizeof(float));

    dim3 grid(DD / TD, WW / TW, BB * (HH / TH));   // (5, 12, 20) = 1200 CTAs
    dim3 block(32, 32, 1);                          // 1024 threads
    deform3d_tile10_kernel<<<grid, block, SVOL * sizeof(float)>>>(X, def, out);
}